// round 8
// baseline (speedup 1.0000x reference)
#include <cuda_runtime.h>
#include <cstdint>

#define P_CHDROP 0.1f
#define NOISE_STD 0.02f
#define P_TIMEMASK 0.1f
#define T_DIM 2048
#define MLEN 32

// R5 structure with 512-thread CTAs: 2 float4/thread, 1024-vec flat tile,
// __ldcs/__stcs streaming, block-uniform per-sample mask params.
// Each tile spans one b (64 blocks per b: 2048*32/1024).
__global__ void __launch_bounds__(512, 4)
eeg_augment_kernel(const float4* __restrict__ x,
                   const float4* __restrict__ chdrop_u,   // [B,32] float4 view of [B,1,N]
                   const float4* __restrict__ noise,
                   const float* __restrict__ tm_u,        // [B]
                   const int* __restrict__ t0,            // [B]
                   float4* __restrict__ out)
{
    const unsigned int blk  = blockIdx.x;
    const unsigned int b    = blk >> 6;                // 64 blocks per b
    const unsigned int base = blk * 1024u + threadIdx.x;

    // Block-uniform per-sample mask parameters
    const bool  apply = __ldg(tm_u + b) < P_TIMEMASK;
    const int   ts    = __ldg(t0 + b);

    const float4* __restrict__ cu_row = chdrop_u + (b << 5);

    #pragma unroll
    for (int k = 0; k < 2; k++) {
        unsigned int i  = base + (unsigned int)k * 512u;
        unsigned int n4 = i & 31u;                     // float4 index within N
        int          t  = (int)((i >> 5) & (T_DIM - 1));

        bool masked = apply & (t >= ts) & (t < ts + MLEN);

        float4 o;
        if (masked) {
            o.x = 0.0f; o.y = 0.0f; o.z = 0.0f; o.w = 0.0f;
        } else {
            float4 xv = __ldcs(x + i);
            float4 nv = __ldcs(noise + i);
            float4 cu = __ldg(cu_row + n4);            // tiny, L1-resident

            o.x = (cu.x < P_CHDROP ? 0.0f : xv.x) + NOISE_STD * nv.x;
            o.y = (cu.y < P_CHDROP ? 0.0f : xv.y) + NOISE_STD * nv.y;
            o.z = (cu.z < P_CHDROP ? 0.0f : xv.z) + NOISE_STD * nv.z;
            o.w = (cu.w < P_CHDROP ? 0.0f : xv.w) + NOISE_STD * nv.w;
        }
        __stcs(out + i, o);
    }
}

extern "C" void kernel_launch(void* const* d_in, const int* in_sizes, int n_in,
                              void* d_out, int out_size)
{
    // metadata order: x, chdrop_u, noise, tm_u, t0
    const float4* x      = (const float4*)d_in[0];
    const float4* cu     = (const float4*)d_in[1];
    const float4* noise  = (const float4*)d_in[2];
    const float*  tm_u   = (const float*)d_in[3];
    const int*    t0     = (const int*)d_in[4];
    float4*       out    = (float4*)d_out;

    // 16,777,216 float4 total; 1024 per block -> 16384 blocks of 512 threads
    eeg_augment_kernel<<<16384u, 512u>>>(x, cu, noise, tm_u, t0, out);
}

// round 9
// speedup vs baseline: 1.0005x; 1.0005x over previous
#include <cuda_runtime.h>
#include <cstdint>

#define P_CHDROP 0.1f
#define NOISE_STD 0.02f
#define P_TIMEMASK 0.1f
#define T_DIM 2048
#define MLEN 32

// FINAL (session best, reproduced 3x at 116.8us bench / 111.4-112.2us ncu):
// - 2 float4/thread in a 512-vec flat block tile (i, i+256) — fully coalesced
// - __ldcs/__stcs streaming hints on the three 256MB zero-reuse streams
// - block-uniform per-sample mask params (each block lies in one b)
// - chdrop row kept L1-resident via __ldg
// At the HBM roofline: 768 MB moved at ~6.88 TB/s (86.8% DRAM active).
__global__ void __launch_bounds__(256, 8)
eeg_augment_kernel(const float4* __restrict__ x,
                   const float4* __restrict__ chdrop_u,   // [B,32] float4 view of [B,1,N]
                   const float4* __restrict__ noise,
                   const float* __restrict__ tm_u,        // [B]
                   const int* __restrict__ t0,            // [B]
                   float4* __restrict__ out)
{
    const unsigned int blk = blockIdx.x;
    const unsigned int b   = blk >> 7;                 // 128 blocks per b (2048*32/512)
    const unsigned int base = blk * 512u + threadIdx.x;

    // Block-uniform per-sample mask parameters (uniform-register loads)
    const bool  apply = __ldg(tm_u + b) < P_TIMEMASK;
    const int   ts    = __ldg(t0 + b);

    const float4* __restrict__ cu_row = chdrop_u + (b << 5);

    #pragma unroll
    for (int k = 0; k < 2; k++) {
        unsigned int i  = base + (unsigned int)k * 256u;
        unsigned int n4 = i & 31u;                     // float4 index within N
        int          t  = (int)((i >> 5) & (T_DIM - 1));

        bool masked = apply & (t >= ts) & (t < ts + MLEN);

        float4 o;
        if (masked) {
            o.x = 0.0f; o.y = 0.0f; o.z = 0.0f; o.w = 0.0f;
        } else {
            float4 xv = __ldcs(x + i);
            float4 nv = __ldcs(noise + i);
            float4 cu = __ldg(cu_row + n4);            // tiny, L1-resident

            o.x = (cu.x < P_CHDROP ? 0.0f : xv.x) + NOISE_STD * nv.x;
            o.y = (cu.y < P_CHDROP ? 0.0f : xv.y) + NOISE_STD * nv.y;
            o.z = (cu.z < P_CHDROP ? 0.0f : xv.z) + NOISE_STD * nv.z;
            o.w = (cu.w < P_CHDROP ? 0.0f : xv.w) + NOISE_STD * nv.w;
        }
        __stcs(out + i, o);
    }
}

extern "C" void kernel_launch(void* const* d_in, const int* in_sizes, int n_in,
                              void* d_out, int out_size)
{
    // metadata order: x, chdrop_u, noise, tm_u, t0
    const float4* x      = (const float4*)d_in[0];
    const float4* cu     = (const float4*)d_in[1];
    const float4* noise  = (const float4*)d_in[2];
    const float*  tm_u   = (const float*)d_in[3];
    const int*    t0     = (const int*)d_in[4];
    float4*       out    = (float4*)d_out;

    // 256*2048*128 f32 = 16,777,216 float4; 512 per block -> 32768 blocks
    eeg_augment_kernel<<<32768u, 256u>>>(x, cu, noise, tm_u, t0, out);
}

// round 10
// speedup vs baseline: 1.0008x; 1.0003x over previous
#include <cuda_runtime.h>
#include <cstdint>

#define P_CHDROP 0.1f
#define NOISE_STD 0.02f
#define P_TIMEMASK 0.1f
#define T_DIM 2048
#define MLEN 32

// FINAL (session best, reproduced 4x at 116.8us bench / 111.4-112.3us ncu):
// - 2 float4/thread in a 512-vec flat block tile (i, i+256) — fully coalesced
// - __ldcs/__stcs streaming hints on the three 256MB zero-reuse streams
// - block-uniform per-sample mask params (each block lies in one b)
// - chdrop row kept L1-resident via __ldg
// At the HBM roofline: 768 MB moved at ~6.85 TB/s (86-87% DRAM active);
// analytic bound 768MB/6.88TB/s = 111.6us == measured ncu kernel time.
__global__ void __launch_bounds__(256, 8)
eeg_augment_kernel(const float4* __restrict__ x,
                   const float4* __restrict__ chdrop_u,   // [B,32] float4 view of [B,1,N]
                   const float4* __restrict__ noise,
                   const float* __restrict__ tm_u,        // [B]
                   const int* __restrict__ t0,            // [B]
                   float4* __restrict__ out)
{
    const unsigned int blk = blockIdx.x;
    const unsigned int b   = blk >> 7;                 // 128 blocks per b (2048*32/512)
    const unsigned int base = blk * 512u + threadIdx.x;

    // Block-uniform per-sample mask parameters (uniform-register loads)
    const bool  apply = __ldg(tm_u + b) < P_TIMEMASK;
    const int   ts    = __ldg(t0 + b);

    const float4* __restrict__ cu_row = chdrop_u + (b << 5);

    #pragma unroll
    for (int k = 0; k < 2; k++) {
        unsigned int i  = base + (unsigned int)k * 256u;
        unsigned int n4 = i & 31u;                     // float4 index within N
        int          t  = (int)((i >> 5) & (T_DIM - 1));

        bool masked = apply & (t >= ts) & (t < ts + MLEN);

        float4 o;
        if (masked) {
            o.x = 0.0f; o.y = 0.0f; o.z = 0.0f; o.w = 0.0f;
        } else {
            float4 xv = __ldcs(x + i);
            float4 nv = __ldcs(noise + i);
            float4 cu = __ldg(cu_row + n4);            // tiny, L1-resident

            o.x = (cu.x < P_CHDROP ? 0.0f : xv.x) + NOISE_STD * nv.x;
            o.y = (cu.y < P_CHDROP ? 0.0f : xv.y) + NOISE_STD * nv.y;
            o.z = (cu.z < P_CHDROP ? 0.0f : xv.z) + NOISE_STD * nv.z;
            o.w = (cu.w < P_CHDROP ? 0.0f : xv.w) + NOISE_STD * nv.w;
        }
        __stcs(out + i, o);
    }
}

extern "C" void kernel_launch(void* const* d_in, const int* in_sizes, int n_in,
                              void* d_out, int out_size)
{
    // metadata order: x, chdrop_u, noise, tm_u, t0
    const float4* x      = (const float4*)d_in[0];
    const float4* cu     = (const float4*)d_in[1];
    const float4* noise  = (const float4*)d_in[2];
    const float*  tm_u   = (const float*)d_in[3];
    const int*    t0     = (const int*)d_in[4];
    float4*       out    = (float4*)d_out;

    // 256*2048*128 f32 = 16,777,216 float4; 512 per block -> 32768 blocks
    eeg_augment_kernel<<<32768u, 256u>>>(x, cu, noise, tm_u, t0, out);
}